// round 1
// baseline (speedup 1.0000x reference)
#include <cuda_runtime.h>
#include <cuda_bf16.h>

// DETR post-processor, single-pass speculative top-k.
//
// Per batch n (256 total):
//   keys = order-preserving uint transform of logits[n] (80000 values)
//   candidates = { i : key_i >= key(2.25f) }   (~980 expected for N(0,1) logits)
//   if #candidates in [300, 4096]: top-300 == top-300 of candidates (proof:
//     all non-candidates < threshold <= all candidates)
//   else: exact histogram fallback (2 more passes; dead path for this input)
//   rank by counting (matches jax.lax.top_k descending order + low-index ties)
//   out[n][r] = [label, sigmoid(logit), (cx-w/2)*fx, (cy-h/2)*fy, w*fx, h*fy]
//   with fx = (float)original_sizes[0][1], fy = (float)original_sizes[0][0]
//   (reference uses batch 0's sizes for ALL batches).

#define THREADS 512
#define TOPK    300
#define NCLS    80
#define NQ      1000
#define NPB     (NQ * NCLS)   // 80000 logits per batch
#define CAP     4096
#define NHIST   4096

__device__ __forceinline__ unsigned fkey(float f) {
    unsigned u = __float_as_uint(f);
    // monotonic: larger float -> larger unsigned
    return (u & 0x80000000u) ? ~u : (u | 0x80000000u);
}

__device__ __forceinline__ float key2f(unsigned k) {
    return (k & 0x80000000u) ? __uint_as_float(k & 0x7fffffffu)
                             : __uint_as_float(~k);
}

__global__ __launch_bounds__(THREADS, 2)
void detr_topk_kernel(const float* __restrict__ logits,
                      const float* __restrict__ boxes,
                      const int*   __restrict__ sizes,
                      float*       __restrict__ out)
{
    __shared__ unsigned s_keys[CAP];
    __shared__ unsigned s_idx[CAP];
    __shared__ unsigned s_hist[NHIST];
    __shared__ int      s_count;
    __shared__ unsigned s_tk;

    const int n   = blockIdx.x;
    const int tid = threadIdx.x;
    const float4* lg4 = reinterpret_cast<const float4*>(logits) + (size_t)n * (NPB / 4);

    if (tid == 0) s_count = 0;
    __syncthreads();

    // ---------- pass 1: speculative candidate collection (the only pass
    // over logits in the expected case) ----------
    const unsigned t0 = fkey(2.25f);

    for (int i = tid; i < NPB / 4; i += THREADS) {
        float4 v = lg4[i];
        unsigned k0 = fkey(v.x), k1 = fkey(v.y), k2 = fkey(v.z), k3 = fkey(v.w);
        if (k0 >= t0) { int p = atomicAdd(&s_count, 1); if (p < CAP) { s_keys[p] = k0; s_idx[p] = 4u * i + 0u; } }
        if (k1 >= t0) { int p = atomicAdd(&s_count, 1); if (p < CAP) { s_keys[p] = k1; s_idx[p] = 4u * i + 1u; } }
        if (k2 >= t0) { int p = atomicAdd(&s_count, 1); if (p < CAP) { s_keys[p] = k2; s_idx[p] = 4u * i + 2u; } }
        if (k3 >= t0) { int p = atomicAdd(&s_count, 1); if (p < CAP) { s_keys[p] = k3; s_idx[p] = 4u * i + 3u; } }
    }
    __syncthreads();
    int cnt = s_count;

    // ---------- exact fallback (statistically unreachable for this input,
    // but keeps the kernel correct for any data) ----------
    if (cnt < TOPK || cnt > CAP) {
        for (int i = tid; i < NHIST; i += THREADS) s_hist[i] = 0u;
        __syncthreads();
        for (int i = tid; i < NPB / 4; i += THREADS) {
            float4 v = lg4[i];
            atomicAdd(&s_hist[fkey(v.x) >> 20], 1u);
            atomicAdd(&s_hist[fkey(v.y) >> 20], 1u);
            atomicAdd(&s_hist[fkey(v.z) >> 20], 1u);
            atomicAdd(&s_hist[fkey(v.w) >> 20], 1u);
        }
        __syncthreads();
        if (tid == 0) {
            unsigned acc = 0;
            int b = NHIST - 1;
            for (; b > 0; --b) { acc += s_hist[b]; if (acc >= TOPK) break; }
            s_tk    = (unsigned)b << 20;
            s_count = 0;
        }
        __syncthreads();
        const unsigned tk = s_tk;
        for (int i = tid; i < NPB / 4; i += THREADS) {
            float4 v = lg4[i];
            unsigned k0 = fkey(v.x), k1 = fkey(v.y), k2 = fkey(v.z), k3 = fkey(v.w);
            if (k0 >= tk) { int p = atomicAdd(&s_count, 1); if (p < CAP) { s_keys[p] = k0; s_idx[p] = 4u * i + 0u; } }
            if (k1 >= tk) { int p = atomicAdd(&s_count, 1); if (p < CAP) { s_keys[p] = k1; s_idx[p] = 4u * i + 1u; } }
            if (k2 >= tk) { int p = atomicAdd(&s_count, 1); if (p < CAP) { s_keys[p] = k2; s_idx[p] = 4u * i + 2u; } }
            if (k3 >= tk) { int p = atomicAdd(&s_count, 1); if (p < CAP) { s_keys[p] = k3; s_idx[p] = 4u * i + 3u; } }
        }
        __syncthreads();
        cnt = s_count;
        if (cnt > CAP) cnt = CAP;
    }

    // ---------- rank-by-counting + epilogue ----------
    const float fx = (float)sizes[1];  // original_sizes[0][::-1] -> x scale
    const float fy = (float)sizes[0];  //                         -> y scale
    const float4* bx4  = reinterpret_cast<const float4*>(boxes) + (size_t)n * NQ;
    float*        outn = out + (size_t)n * TOPK * 6;

    for (int i = tid; i < cnt; i += THREADS) {
        const unsigned ki = s_keys[i];
        const unsigned ii = s_idx[i];
        int rank = 0;
        for (int j = 0; j < cnt; j++) {
            const unsigned kj = s_keys[j];
            if (kj > ki) rank++;
            else if (kj == ki && s_idx[j] < ii) rank++;
        }
        if (rank < TOPK) {
            const float lv    = key2f(ki);
            const float score = 1.0f / (1.0f + __expf(-lv));
            const unsigned q   = ii / NCLS;
            const unsigned lbl = ii - q * NCLS;
            const float4 b = bx4[q];  // [cx, cy, w, h]
            float* o = outn + rank * 6;
            o[0] = (float)lbl;
            o[1] = score;
            o[2] = (b.x - 0.5f * b.z) * fx;
            o[3] = (b.y - 0.5f * b.w) * fy;
            o[4] = b.z * fx;
            o[5] = b.w * fy;
        }
    }
}

extern "C" void kernel_launch(void* const* d_in, const int* in_sizes, int n_in,
                              void* d_out, int out_size)
{
    const float* logits = (const float*)d_in[0];
    const float* boxes  = (const float*)d_in[1];
    const int*   sizes  = (const int*)d_in[2];
    const int    N      = in_sizes[0] / NPB;  // 256
    detr_topk_kernel<<<N, THREADS>>>(logits, boxes, sizes, (float*)d_out);
}

// round 2
// speedup vs baseline: 2.9810x; 2.9810x over previous
#include <cuda_runtime.h>
#include <cuda_bf16.h>

// DETR post-processor, 3-launch pipeline:
//   zero_kernel  : reset per-batch candidate counters
//   scan_kernel  : stream 20.48M logits, rare-branch threshold filter (t=2.4),
//                  candidates -> global scratch as packed u64 (key<<32 | ~idx)
//   rank_kernel  : per batch, bitonic-sort <=1024 candidates descending,
//                  top-300 -> sigmoid + box decode + scaled write.
// Exact histogram fallback in rank_kernel if a batch has <300 or >1024
// candidates (never taken for N(0,1) logits: lambda=656, sigma=26).

#define NCLS    80
#define NQ      1000
#define NPB     80000          // logits per batch
#define NB      256
#define TOPK    300
#define CAP     1024
#define THR     2.4f
#define ATHREADS 512
#define UNROLL   5
#define BTHREADS 512
#define NHIST   4096

__device__ unsigned long long g_cand[NB][CAP];
__device__ int g_cnt[NB];

__device__ __forceinline__ unsigned fkey(float f) {
    unsigned u = __float_as_uint(f);
    return (u & 0x80000000u) ? ~u : (u | 0x80000000u);  // monotonic float->uint
}
__device__ __forceinline__ float key2f(unsigned k) {
    return (k & 0x80000000u) ? __uint_as_float(k & 0x7fffffffu)
                             : __uint_as_float(~k);
}

__global__ void zero_kernel() { g_cnt[threadIdx.x] = 0; }

__global__ __launch_bounds__(ATHREADS, 3)
void scan_kernel(const float4* __restrict__ lg, int total_f4)
{
    const unsigned S  = gridDim.x * (unsigned)ATHREADS;
    const unsigned g0 = blockIdx.x * (unsigned)ATHREADS + threadIdx.x;

    float4   v[UNROLL];
    unsigned ix[UNROLL];
    bool     ok[UNROLL];

    // batch the loads up front for MLP
    #pragma unroll
    for (int k = 0; k < UNROLL; k++) {
        ix[k] = g0 + (unsigned)k * S;
        ok[k] = ix[k] < (unsigned)total_f4;
        if (ok[k]) v[k] = lg[ix[k]];
    }

    #pragma unroll
    for (int k = 0; k < UNROLL; k++) {
        if (!ok[k]) continue;
        const float4 x = v[k];
        const float m = fmaxf(fmaxf(x.x, x.y), fmaxf(x.z, x.w));
        if (m > THR) {                       // ~3.2% of float4s
            const unsigned i4   = ix[k];
            const unsigned n    = i4 / 20000u;          // batch (NPB/4 f4 per batch)
            const unsigned base = (i4 - n * 20000u) * 4u;
            const float e[4] = {x.x, x.y, x.z, x.w};
            #pragma unroll
            for (int j = 0; j < 4; j++) {
                if (e[j] > THR) {
                    const int p = atomicAdd(&g_cnt[n], 1);
                    if (p < CAP) {
                        g_cand[n][p] =
                            ((unsigned long long)fkey(e[j]) << 32) |
                            (unsigned)(0xFFFFFFFFu - (base + (unsigned)j));
                    }
                }
            }
        }
    }
}

__global__ __launch_bounds__(BTHREADS)
void rank_kernel(const float4* __restrict__ lg,
                 const float4* __restrict__ bx,
                 const int*    __restrict__ sizes,
                 float*        __restrict__ out)
{
    __shared__ unsigned long long s[CAP];
    __shared__ unsigned s_hist[NHIST];
    __shared__ int s_c;
    __shared__ unsigned s_tk;

    const int n   = blockIdx.x;
    const int tid = threadIdx.x;
    int cnt = g_cnt[n];

    if (cnt >= TOPK && cnt <= CAP) {
        // expected path: load candidates, pad with 0 (< any candidate key)
        for (int i = tid; i < CAP; i += BTHREADS)
            s[i] = (i < cnt) ? g_cand[n][i] : 0ULL;
    } else {
        // ---- exact fallback: histogram threshold + recollect (dead path) ----
        const float4* base = lg + (size_t)n * (NPB / 4);
        for (int i = tid; i < NHIST; i += BTHREADS) s_hist[i] = 0u;
        if (tid == 0) s_c = 0;
        __syncthreads();
        for (int i = tid; i < NPB / 4; i += BTHREADS) {
            float4 v = base[i];
            atomicAdd(&s_hist[fkey(v.x) >> 20], 1u);
            atomicAdd(&s_hist[fkey(v.y) >> 20], 1u);
            atomicAdd(&s_hist[fkey(v.z) >> 20], 1u);
            atomicAdd(&s_hist[fkey(v.w) >> 20], 1u);
        }
        __syncthreads();
        if (tid == 0) {
            unsigned acc = 0; int b = NHIST - 1;
            for (; b > 0; --b) { acc += s_hist[b]; if (acc >= TOPK) break; }
            s_tk = (unsigned)b << 20;
        }
        __syncthreads();
        const unsigned tk = s_tk;
        for (int i = tid; i < NPB / 4; i += BTHREADS) {
            float4 v = base[i];
            const float e[4] = {v.x, v.y, v.z, v.w};
            #pragma unroll
            for (int j = 0; j < 4; j++) {
                unsigned kk = fkey(e[j]);
                if (kk >= tk) {
                    int p = atomicAdd(&s_c, 1);
                    if (p < CAP)
                        s[p] = ((unsigned long long)kk << 32) |
                               (unsigned)(0xFFFFFFFFu - (unsigned)(4 * i + j));
                }
            }
        }
        __syncthreads();
        cnt = min(s_c, CAP);
        for (int i = cnt + tid; i < CAP; i += BTHREADS) s[i] = 0ULL;
    }
    __syncthreads();

    // ---- bitonic sort, descending, 1024 elements, 512 threads ----
    #pragma unroll 1
    for (int k = 2; k <= CAP; k <<= 1) {
        #pragma unroll 1
        for (int j = k >> 1; j > 0; j >>= 1) {
            const int i = ((tid & ~(j - 1)) << 1) | (tid & (j - 1));
            const int l = i | j;
            const unsigned long long a = s[i], b = s[l];
            const bool up = ((i & k) == 0);
            if ((a < b) == up) { s[i] = b; s[l] = a; }
            __syncthreads();
        }
    }

    // ---- epilogue: top-300 decode ----
    if (tid < TOPK) {
        const unsigned long long pk = s[tid];
        const unsigned key  = (unsigned)(pk >> 32);
        const unsigned flat = 0xFFFFFFFFu - (unsigned)(pk & 0xFFFFFFFFu);
        const float lv    = key2f(key);
        const float score = 1.0f / (1.0f + __expf(-lv));
        const unsigned q   = flat / (unsigned)NCLS;
        const unsigned lbl = flat - q * (unsigned)NCLS;
        const float4 b = bx[(size_t)n * NQ + q];           // [cx, cy, w, h]
        const float fx = (float)sizes[1];
        const float fy = (float)sizes[0];
        float2* o = reinterpret_cast<float2*>(out + ((size_t)n * TOPK + tid) * 6);
        o[0] = make_float2((float)lbl, score);
        o[1] = make_float2((b.x - 0.5f * b.z) * fx, (b.y - 0.5f * b.w) * fy);
        o[2] = make_float2(b.z * fx, b.w * fy);
    }
}

extern "C" void kernel_launch(void* const* d_in, const int* in_sizes, int n_in,
                              void* d_out, int out_size)
{
    const float* logits = (const float*)d_in[0];
    const float* boxes  = (const float*)d_in[1];
    const int*   sizes  = (const int*)d_in[2];
    const int total_f4  = in_sizes[0] / 4;                     // 5,120,000
    const int grid      = (total_f4 + ATHREADS * UNROLL - 1) / (ATHREADS * UNROLL); // 2000

    zero_kernel<<<1, NB>>>();
    scan_kernel<<<grid, ATHREADS>>>((const float4*)logits, total_f4);
    rank_kernel<<<NB, BTHREADS>>>((const float4*)logits, (const float4*)boxes,
                                  sizes, (float*)d_out);
}